// round 1
// baseline (speedup 1.0000x reference)
#include <cuda_runtime.h>
#include <math.h>

#define NROWS 32768
#define C 128          // in/out channels = head dim
#define H 8            // heads
#define PITCH 132      // smem pitch (floats); 132*4B multiple of 16 for float4
#define TS (128 * PITCH)
#define NC 64          // K2 row chunks
#define SUBT 4         // 128-row sub-tiles per chunk (64*4*128 = 32768)

// ---------------- scratch (device globals; no allocations allowed) ----------------
__device__ float g_phiq[(size_t)NROWS * H * C];        // [n][h][m]   134 MB
__device__ float g_ktv_part[NC * H * C * C];           // [c][h][m][d] 33.5 MB
__device__ float g_kss_part[NC * H * C];               // [c][h][m]
__device__ float g_ktv[H * C * C];                     // [h][m][d]
__device__ float g_kss[H * C];                         // [h][m]
__device__ float g_Wcomb[C * C];                       // [o][i]
__device__ float g_bcomb[C];

// ---------------- helpers ----------------
// Load a 128x128 fp32 tile (row-major, row stride C) TRANSPOSED: s[i][r] = g[r*C+i]
__device__ __forceinline__ void load_tile_T(float* s, const float* __restrict__ g) {
    int tid = threadIdx.x;
#pragma unroll
    for (int it = 0; it < 16; it++) {
        int idx = tid + it * 256;
        int r = idx >> 5;
        int i0 = (idx & 31) << 2;
        float4 v = *(const float4*)(g + (size_t)r * C + i0);
        s[(i0 + 0) * PITCH + r] = v.x;
        s[(i0 + 1) * PITCH + r] = v.y;
        s[(i0 + 2) * PITCH + r] = v.z;
        s[(i0 + 3) * PITCH + r] = v.w;
    }
}

// Load a 128x128 tile straight (already k-major): s[k][d] = g[k*C+d]
__device__ __forceinline__ void load_tile_D(float* s, const float* __restrict__ g) {
    int tid = threadIdx.x;
#pragma unroll
    for (int it = 0; it < 16; it++) {
        int idx = tid + it * 256;
        int k = idx >> 5;
        int d0 = (idx & 31) << 2;
        *(float4*)(s + k * PITCH + d0) = *(const float4*)(g + (size_t)k * C + d0);
    }
}

// 128x128x128 register-tiled GEMM: acc[j][k] += sum_k sA[k][m0+j]*sB[k][o0+kk]
__device__ __forceinline__ void gemm_tile(const float* __restrict__ sA,
                                          const float* __restrict__ sB,
                                          float acc[8][8], int m0, int o0) {
#pragma unroll 4
    for (int k = 0; k < 128; k++) {
        const float* pa = sA + k * PITCH + m0;
        const float* pb = sB + k * PITCH + o0;
        float4 a0 = *(const float4*)(pa);
        float4 a1 = *(const float4*)(pa + 4);
        float4 b0 = *(const float4*)(pb);
        float4 b1 = *(const float4*)(pb + 4);
        float a[8] = {a0.x, a0.y, a0.z, a0.w, a1.x, a1.y, a1.z, a1.w};
        float b[8] = {b0.x, b0.y, b0.z, b0.w, b1.x, b1.y, b1.z, b1.w};
#pragma unroll
        for (int j = 0; j < 8; j++)
#pragma unroll
            for (int kk = 0; kk < 8; kk++)
                acc[j][kk] += a[j] * b[kk];
    }
}

__device__ __forceinline__ float inv_denom_scale(const float* ns) {
    return 1.0f / (fabsf(ns[0]) + 1e-6f);
}

// ---------------- K1: qs = query @ Wq[h]^T + b ; phi ; write g_phiq ----------------
__global__ void __launch_bounds__(256, 1)
k1_qphi(const float* __restrict__ q, const float* __restrict__ Wq,
        const float* __restrict__ Wqb, const float* __restrict__ ns) {
    extern __shared__ float sm[];
    float* sA = sm;            // queryT
    float* sB = sm + TS;       // WqT
    float* sC = sm + 2 * TS;   // qs tile
    int t = blockIdx.x, h = blockIdx.y;
    int n0 = t * 128;
    int tid = threadIdx.x;
    int tc = tid & 15, tr = tid >> 4;
    int m0 = tr * 8, o0 = tc * 8;
    int lane = tid & 31, w = tid >> 5;

    load_tile_T(sA, q + (size_t)n0 * C);
    load_tile_T(sB, Wq + (size_t)h * C * C);
    __syncthreads();

    float acc[8][8];
#pragma unroll
    for (int j = 0; j < 8; j++)
#pragma unroll
        for (int k = 0; k < 8; k++) acc[j][k] = 0.0f;
    gemm_tile(sA, sB, acc, m0, o0);
#pragma unroll
    for (int k = 0; k < 8; k++) {
        float bv = Wqb[h * C + o0 + k];
#pragma unroll
        for (int j = 0; j < 8; j++) acc[j][k] += bv;
    }
#pragma unroll
    for (int j = 0; j < 8; j++) {
        float* p = sC + (m0 + j) * PITCH + o0;
        *(float4*)(p) = make_float4(acc[j][0], acc[j][1], acc[j][2], acc[j][3]);
        *(float4*)(p + 4) = make_float4(acc[j][4], acc[j][5], acc[j][6], acc[j][7]);
    }
    __syncthreads();

    float ids = inv_denom_scale(ns);
    for (int r = w; r < 128; r += 8) {
        float x2[4];
        float s1 = 0.0f, s2 = 0.0f;
#pragma unroll
        for (int k = 0; k < 4; k++) {
            float v = sC[r * PITCH + lane + 32 * k];
            float x = (fmaxf(v, 0.0f) + 1e-6f) * ids;
            float xx = x * x;
            x2[k] = xx;
            s1 += xx;
            s2 += xx * xx;
        }
#pragma unroll
        for (int off = 16; off > 0; off >>= 1) {
            s1 += __shfl_xor_sync(0xffffffffu, s1, off);
            s2 += __shfl_xor_sync(0xffffffffu, s2, off);
        }
        float scale = sqrtf(s1) / (sqrtf(s2) + 1e-8f);
        size_t base = ((size_t)(n0 + r) * H + h) * C;
#pragma unroll
        for (int k = 0; k < 4; k++)
            g_phiq[base + lane + 32 * k] = x2[k] * scale;
    }
}

// ---------------- K2: per (chunk,head): ks,v -> phi_k -> KtV + kssum partials ----------------
__global__ void __launch_bounds__(256, 1)
k2_kv(const float* __restrict__ src,
      const float* __restrict__ Wk, const float* __restrict__ Wkb,
      const float* __restrict__ Wv, const float* __restrict__ Wvb,
      const float* __restrict__ ns) {
    extern __shared__ float sm[];
    float* sA = sm;            // srcT
    float* sB = sm + TS;       // WkT / WvT / v tile
    float* sC = sm + 2 * TS;   // ks / phi_k tile
    int c = blockIdx.x, h = blockIdx.y;
    int tid = threadIdx.x;
    int tc = tid & 15, tr = tid >> 4;
    int m0 = tr * 8, o0 = tc * 8;
    int lane = tid & 31, w = tid >> 5;
    float ids = inv_denom_scale(ns);

    float acc2[8][8];
#pragma unroll
    for (int j = 0; j < 8; j++)
#pragma unroll
        for (int k = 0; k < 8; k++) acc2[j][k] = 0.0f;
    float kss = 0.0f;  // column sum (valid for tid<128, col=tid)

    for (int s = 0; s < SUBT; s++) {
        int n0 = (c * SUBT + s) * 128;
        __syncthreads();  // prior iter done reading sA/sB/sC
        load_tile_T(sA, src + (size_t)n0 * C);
        load_tile_T(sB, Wk + (size_t)h * C * C);
        __syncthreads();

        // ks GEMM
        float acc[8][8];
#pragma unroll
        for (int j = 0; j < 8; j++)
#pragma unroll
            for (int k = 0; k < 8; k++) acc[j][k] = 0.0f;
        gemm_tile(sA, sB, acc, m0, o0);
#pragma unroll
        for (int k = 0; k < 8; k++) {
            float bv = Wkb[h * C + o0 + k];
#pragma unroll
            for (int j = 0; j < 8; j++) acc[j][k] += bv;
        }
#pragma unroll
        for (int j = 0; j < 8; j++) {
            float* p = sC + (m0 + j) * PITCH + o0;
            *(float4*)(p) = make_float4(acc[j][0], acc[j][1], acc[j][2], acc[j][3]);
            *(float4*)(p + 4) = make_float4(acc[j][4], acc[j][5], acc[j][6], acc[j][7]);
        }
        __syncthreads();

        // phi_k in place; overwrite sB with WvT (safe: all past ks gemm)
        for (int r = w; r < 128; r += 8) {
            float x2[4];
            float s1 = 0.0f, s2 = 0.0f;
#pragma unroll
            for (int k = 0; k < 4; k++) {
                float v = sC[r * PITCH + lane + 32 * k];
                float x = (fmaxf(v, 0.0f) + 1e-6f) * ids;
                float xx = x * x;
                x2[k] = xx;
                s1 += xx;
                s2 += xx * xx;
            }
#pragma unroll
            for (int off = 16; off > 0; off >>= 1) {
                s1 += __shfl_xor_sync(0xffffffffu, s1, off);
                s2 += __shfl_xor_sync(0xffffffffu, s2, off);
            }
            float scale = sqrtf(s1) / (sqrtf(s2) + 1e-8f);
#pragma unroll
            for (int k = 0; k < 4; k++)
                sC[r * PITCH + lane + 32 * k] = x2[k] * scale;
        }
        load_tile_T(sB, Wv + (size_t)h * C * C);
        __syncthreads();

        // kssum column accumulation
        if (tid < 128) {
            float s0 = 0.0f;
#pragma unroll 8
            for (int r = 0; r < 128; r++) s0 += sC[r * PITCH + tid];
            kss += s0;
        }

        // v GEMM
#pragma unroll
        for (int j = 0; j < 8; j++)
#pragma unroll
            for (int k = 0; k < 8; k++) acc[j][k] = 0.0f;
        gemm_tile(sA, sB, acc, m0, o0);
#pragma unroll
        for (int k = 0; k < 8; k++) {
            float bv = Wvb[h * C + o0 + k];
#pragma unroll
            for (int j = 0; j < 8; j++) acc[j][k] += bv;
        }
        __syncthreads();  // all v-gemm reads of sB done
#pragma unroll
        for (int j = 0; j < 8; j++) {
            float* p = sB + (m0 + j) * PITCH + o0;
            *(float4*)(p) = make_float4(acc[j][0], acc[j][1], acc[j][2], acc[j][3]);
            *(float4*)(p + 4) = make_float4(acc[j][4], acc[j][5], acc[j][6], acc[j][7]);
        }
        __syncthreads();

        // ktv GEMM: acc2[m][d] += sum_r phi_k[r][m] * v[r][d]
        gemm_tile(sC, sB, acc2, m0, o0);
    }

    // write partials
    size_t base = ((size_t)(c * H + h)) * C * C;
#pragma unroll
    for (int j = 0; j < 8; j++) {
        float* p = g_ktv_part + base + (size_t)(m0 + j) * C + o0;
        *(float4*)(p) = make_float4(acc2[j][0], acc2[j][1], acc2[j][2], acc2[j][3]);
        *(float4*)(p + 4) = make_float4(acc2[j][4], acc2[j][5], acc2[j][6], acc2[j][7]);
    }
    if (tid < 128)
        g_kss_part[(size_t)(c * H + h) * C + tid] = kss;
}

// ---------------- K2b: reduce partials over chunks ----------------
__global__ void k2b_reduce() {
    int i = blockIdx.x * blockDim.x + threadIdx.x;  // 0..H*C*C-1
    float s = 0.0f;
#pragma unroll 8
    for (int c = 0; c < NC; c++) s += g_ktv_part[(size_t)c * (H * C * C) + i];
    g_ktv[i] = s;
    if (i < H * C) {
        float s2 = 0.0f;
#pragma unroll 8
        for (int c = 0; c < NC; c++) s2 += g_kss_part[(size_t)c * (H * C) + i];
        g_kss[i] = s2;
    }
}

// ---------------- Kw: Wcomb = v_map @ mean_h(Wv), bcomb ----------------
__global__ void __launch_bounds__(256, 1)
kw_comb(const float* __restrict__ Wv, const float* __restrict__ Wvb,
        const float* __restrict__ vmap, const float* __restrict__ vmapb) {
    extern __shared__ float sm[];
    float* sWb = sm;  // Wvbar [d][i], pitch PITCH
    int tid = threadIdx.x;
    int lane = tid & 31, w = tid >> 5;
#pragma unroll
    for (int it = 0; it < 64; it++) {
        int idx = tid + it * 256;
        int d = idx >> 7, i = idx & 127;
        float s = 0.0f;
#pragma unroll
        for (int h = 0; h < H; h++) s += Wv[((size_t)h * C + d) * C + i];
        sWb[d * PITCH + i] = s * 0.125f;
    }
    __syncthreads();

    int o = blockIdx.x * 8 + w;  // 16 blocks x 8 warps -> 128 rows
    float r[4] = {0.0f, 0.0f, 0.0f, 0.0f};
    for (int d = 0; d < 128; d++) {
        float vm = vmap[(size_t)o * C + d];
#pragma unroll
        for (int k = 0; k < 4; k++) r[k] += vm * sWb[d * PITCH + lane + 32 * k];
    }
#pragma unroll
    for (int k = 0; k < 4; k++) g_Wcomb[(size_t)o * C + lane + 32 * k] = r[k];

    if (blockIdx.x == 0 && tid < 128) {
        int oo = tid;
        float s = 0.0f;
        for (int d = 0; d < 128; d++) {
            float bv = 0.0f;
#pragma unroll
            for (int h = 0; h < H; h++) bv += Wvb[h * C + d];
            s += vmap[(size_t)oo * C + d] * (bv * 0.125f);
        }
        g_bcomb[oo] = s + vmapb[oo];
    }
}

// ---------------- K3: numerator GEMMs + denom + comb GEMM + epilogue ----------------
__global__ void __launch_bounds__(256, 1)
k3_out(const float* __restrict__ src, float* __restrict__ out) {
    extern __shared__ float sm[];
    float* sA = sm;
    float* sB = sm + TS;
    float* sC = sm + 2 * TS;
    float* kss_s = sm + 3 * TS;
    float* den_s = kss_s + 128;
    int t = blockIdx.x;
    int n0 = t * 128;
    int tid = threadIdx.x;
    int tc = tid & 15, tr = tid >> 4;
    int m0 = tr * 8, o0 = tc * 8;
    int lane = tid & 31, w = tid >> 5;

    float outacc[8][8];
#pragma unroll
    for (int j = 0; j < 8; j++)
#pragma unroll
        for (int k = 0; k < 8; k++) outacc[j][k] = 0.0f;

    for (int h = 0; h < H; h++) {
        __syncthreads();
        // transposed load of phi_q tile: sA[mm][row]
#pragma unroll
        for (int it = 0; it < 16; it++) {
            int idx = tid + it * 256;
            int r = idx >> 5;
            int i0 = (idx & 31) << 2;
            float4 v = *(const float4*)(g_phiq + ((size_t)(n0 + r) * H + h) * C + i0);
            sA[(i0 + 0) * PITCH + r] = v.x;
            sA[(i0 + 1) * PITCH + r] = v.y;
            sA[(i0 + 2) * PITCH + r] = v.z;
            sA[(i0 + 3) * PITCH + r] = v.w;
        }
        load_tile_D(sB, g_ktv + (size_t)h * C * C);
        if (tid < 128) kss_s[tid] = g_kss[h * C + tid];
        __syncthreads();

        if (tid < 128) {
            float d = 0.0f;
#pragma unroll 8
            for (int mm = 0; mm < 128; mm++) d += sA[mm * PITCH + tid] * kss_s[mm];
            den_s[tid] = 0.125f / (d + 1e-6f);
        }
        __syncthreads();

        float acc[8][8];
#pragma unroll
        for (int j = 0; j < 8; j++)
#pragma unroll
            for (int k = 0; k < 8; k++) acc[j][k] = 0.0f;
        gemm_tile(sA, sB, acc, m0, o0);
#pragma unroll
        for (int j = 0; j < 8; j++) {
            float sc = den_s[m0 + j];
#pragma unroll
            for (int k = 0; k < 8; k++) outacc[j][k] += acc[j][k] * sc;
        }
    }

    __syncthreads();
    // comb GEMM (vss head-mean folded into src @ Wcomb^T + bcomb)
    load_tile_T(sA, src + (size_t)n0 * C);
    load_tile_T(sB, g_Wcomb);
    __syncthreads();
    {
        float acc[8][8];
#pragma unroll
        for (int j = 0; j < 8; j++)
#pragma unroll
            for (int k = 0; k < 8; k++) acc[j][k] = 0.0f;
        gemm_tile(sA, sB, acc, m0, o0);
#pragma unroll
        for (int k = 0; k < 8; k++) {
            float bc = g_bcomb[o0 + k];
#pragma unroll
            for (int j = 0; j < 8; j++) outacc[j][k] += acc[j][k] + bc;
        }
    }
    __syncthreads();
#pragma unroll
    for (int j = 0; j < 8; j++) {
        float* p = sC + (m0 + j) * PITCH + o0;
        *(float4*)(p) = make_float4(outacc[j][0], outacc[j][1], outacc[j][2], outacc[j][3]);
        *(float4*)(p + 4) = make_float4(outacc[j][4], outacc[j][5], outacc[j][6], outacc[j][7]);
    }
    __syncthreads();

    // epilogue: time coordinate + interleaved [time, 128 feats] rows
    for (int r = w; r < 128; r += 8) {
        float v[4];
        float ss = 0.0f;
#pragma unroll
        for (int k = 0; k < 4; k++) {
            v[k] = sC[r * PITCH + lane + 32 * k];
            ss += v[k] * v[k];
        }
#pragma unroll
        for (int off = 16; off > 0; off >>= 1)
            ss += __shfl_xor_sync(0xffffffffu, ss, off);
        float tm = sqrtf(ss + 1.0f);
        float* orow = out + (size_t)(n0 + r) * 129;
        if (lane == 0) orow[0] = tm;
#pragma unroll
        for (int k = 0; k < 4; k++) orow[1 + lane + 32 * k] = v[k];
    }
}

// ---------------- launch ----------------
extern "C" void kernel_launch(void* const* d_in, const int* in_sizes, int n_in,
                              void* d_out, int out_size) {
    const float* q     = (const float*)d_in[0];
    const float* src   = (const float*)d_in[1];
    const float* Wq    = (const float*)d_in[2];
    const float* Wqb   = (const float*)d_in[3];
    const float* Wk    = (const float*)d_in[4];
    const float* Wkb   = (const float*)d_in[5];
    const float* Wv    = (const float*)d_in[6];
    const float* Wvb   = (const float*)d_in[7];
    const float* vmap  = (const float*)d_in[8];
    const float* vmapb = (const float*)d_in[9];
    const float* ns    = (const float*)d_in[10];
    float* out = (float*)d_out;

    size_t smem = (size_t)(3 * TS + 256) * sizeof(float);   // ~203.8 KB
    size_t smem_w = (size_t)TS * sizeof(float);             // ~67.6 KB
    cudaFuncSetAttribute(k1_qphi, cudaFuncAttributeMaxDynamicSharedMemorySize, (int)smem);
    cudaFuncSetAttribute(k2_kv,   cudaFuncAttributeMaxDynamicSharedMemorySize, (int)smem);
    cudaFuncSetAttribute(k3_out,  cudaFuncAttributeMaxDynamicSharedMemorySize, (int)smem);
    cudaFuncSetAttribute(kw_comb, cudaFuncAttributeMaxDynamicSharedMemorySize, (int)smem_w);

    kw_comb<<<16, 256, smem_w>>>(Wv, Wvb, vmap, vmapb);
    k1_qphi<<<dim3(NROWS / 128, H), 256, smem>>>(q, Wq, Wqb, ns);
    k2_kv<<<dim3(NC, H), 256, smem>>>(src, Wk, Wkb, Wv, Wvb, ns);
    k2b_reduce<<<(H * C * C) / 256, 256>>>();
    k3_out<<<NROWS / 128, 256, smem>>>(src, out);
}

// round 2
// speedup vs baseline: 2.7031x; 2.7031x over previous
#include <cuda_runtime.h>
#include <cuda_bf16.h>
#include <math.h>
#include <stdint.h>

#define NROWS 32768
#define C 128
#define H 8
#define KP 136                 // bf16 plane row stride (elements); 272B = 17*16B
#define PLANE (128 * KP)       // elems per 128-row plane (34816 B)
#define NC 64
#define SUBT 4
#define PITCHF 132             // fp32 pitch for kw_comb

// ---------------- scratch ----------------
__device__ uint32_t g_phiq[(size_t)NROWS * H * C];   // packed bf16 hi | lo<<16
__device__ float    g_ktv_part[NC * H * C * C];      // [c][h][m][d]
__device__ float    g_kss_part[NC * H * C];
__device__ uint32_t g_ktvP[H * C * C];               // [h][d][m] packed (B operand)
__device__ float    g_kss[H * C];
__device__ uint32_t g_WcombP[C * C];                 // [o][i] packed
__device__ float    g_bcomb[C];

// ---------------- low-level helpers ----------------
__device__ __forceinline__ uint32_t smem_u32(const void* p) {
    return (uint32_t)__cvta_generic_to_shared(p);
}

__device__ __forceinline__ void ldm4(uint32_t r[4], const __nv_bfloat16* p) {
    uint32_t a = smem_u32(p);
    asm volatile("ldmatrix.sync.aligned.m8n8.x4.shared.b16 {%0,%1,%2,%3}, [%4];"
                 : "=r"(r[0]), "=r"(r[1]), "=r"(r[2]), "=r"(r[3]) : "r"(a));
}

__device__ __forceinline__ void mma_bf16(float d[4], const uint32_t a[4],
                                         uint32_t b0, uint32_t b1) {
    asm volatile(
        "mma.sync.aligned.m16n8k16.row.col.f32.bf16.bf16.f32 "
        "{%0,%1,%2,%3},{%4,%5,%6,%7},{%8,%9},{%0,%1,%2,%3};"
        : "+f"(d[0]), "+f"(d[1]), "+f"(d[2]), "+f"(d[3])
        : "r"(a[0]), "r"(a[1]), "r"(a[2]), "r"(a[3]), "r"(b0), "r"(b1));
}

__device__ __forceinline__ uint32_t packf(float x) {
    __nv_bfloat16 h = __float2bfloat16(x);
    __nv_bfloat16 l = __float2bfloat16(x - __bfloat162float(h));
    return (uint32_t)__bfloat16_as_ushort(h) | ((uint32_t)__bfloat16_as_ushort(l) << 16);
}

__device__ __forceinline__ void split2(__nv_bfloat16* hi, __nv_bfloat16* lo,
                                       int off, float x, float y) {
    __nv_bfloat16 hx = __float2bfloat16(x), hy = __float2bfloat16(y);
    __nv_bfloat16 lx = __float2bfloat16(x - __bfloat162float(hx));
    __nv_bfloat16 ly = __float2bfloat16(y - __bfloat162float(hy));
    *(__nv_bfloat162*)(hi + off) = __halves2bfloat162(hx, hy);
    *(__nv_bfloat162*)(lo + off) = __halves2bfloat162(lx, ly);
}

// fp32 gmem tile [128][ldg] -> two bf16 planes [128][KP]
__device__ __forceinline__ void load_split_tile(const float* __restrict__ g, int ldg,
                                                __nv_bfloat16* hi, __nv_bfloat16* lo) {
    int tid = threadIdx.x;
#pragma unroll
    for (int it = 0; it < 16; it++) {
        int idx = tid + it * 256;
        int r = idx >> 5, c = (idx & 31) << 2;
        float4 v = *(const float4*)(g + (size_t)r * ldg + c);
        int o = r * KP + c;
        split2(hi, lo, o, v.x, v.y);
        split2(hi, lo, o + 2, v.z, v.w);
    }
}

// packed gmem tile [128 rows, stride srow uint32] -> two bf16 planes
__device__ __forceinline__ void load_packed_tile(const uint32_t* __restrict__ g, size_t srow,
                                                 __nv_bfloat16* hi, __nv_bfloat16* lo) {
    int tid = threadIdx.x;
#pragma unroll
    for (int it = 0; it < 16; it++) {
        int idx = tid + it * 256;
        int r = idx >> 5, c = (idx & 31) << 2;
        uint4 v = *(const uint4*)(g + (size_t)r * srow + c);
        int o = r * KP + c;
        hi[o + 0] = __ushort_as_bfloat16((unsigned short)(v.x & 0xffff));
        lo[o + 0] = __ushort_as_bfloat16((unsigned short)(v.x >> 16));
        hi[o + 1] = __ushort_as_bfloat16((unsigned short)(v.y & 0xffff));
        lo[o + 1] = __ushort_as_bfloat16((unsigned short)(v.y >> 16));
        hi[o + 2] = __ushort_as_bfloat16((unsigned short)(v.z & 0xffff));
        lo[o + 2] = __ushort_as_bfloat16((unsigned short)(v.z >> 16));
        hi[o + 3] = __ushort_as_bfloat16((unsigned short)(v.w & 0xffff));
        lo[o + 3] = __ushort_as_bfloat16((unsigned short)(v.w >> 16));
    }
}

// warp GEMM: rows [mrow, mrow+16) x all 128 cols, K=128, split-bf16 (3 mma passes)
// acc[f][j]: frag f covers cols (f>>1)*16 + (f&1)*8 + 2*(lane&3) + {0,1}; rows lane>>2 (+8)
__device__ __forceinline__ void wgemm(float acc[16][4],
                                      const __nv_bfloat16* Ahi, const __nv_bfloat16* Alo,
                                      const __nv_bfloat16* Bhi, const __nv_bfloat16* Blo,
                                      int mrow) {
    int lane = threadIdx.x & 31;
    int lr = lane & 15, lc = lane >> 4;
#pragma unroll
    for (int kt = 0; kt < 8; kt++) {
        int aoff = (mrow + lr) * KP + kt * 16 + lc * 8;
        uint32_t ah[4], al[4];
        ldm4(ah, Ahi + aoff);
        ldm4(al, Alo + aoff);
#pragma unroll
        for (int nt = 0; nt < 8; nt++) {
            int boff = (nt * 16 + lr) * KP + kt * 16 + lc * 8;
            uint32_t bh[4], bl[4];
            ldm4(bh, Bhi + boff);
            ldm4(bl, Blo + boff);
            mma_bf16(acc[nt * 2], ah, bh[0], bh[2]);
            mma_bf16(acc[nt * 2], ah, bl[0], bl[2]);
            mma_bf16(acc[nt * 2], al, bh[0], bh[2]);
            mma_bf16(acc[nt * 2 + 1], ah, bh[1], bh[3]);
            mma_bf16(acc[nt * 2 + 1], ah, bl[1], bl[3]);
            mma_bf16(acc[nt * 2 + 1], al, bh[1], bh[3]);
        }
    }
}

#define ZERO16x4(a)                         \
    _Pragma("unroll") for (int _f = 0; _f < 16; _f++) \
        { a[_f][0] = 0.f; a[_f][1] = 0.f; a[_f][2] = 0.f; a[_f][3] = 0.f; }

// bias + relu + eps + scale + square + row-normalize, entirely in registers
__device__ __forceinline__ void phi_regs(float acc[16][4], const float* bias_s, float ids) {
    int lane = threadIdx.x & 31;
    float s1a = 0.f, s2a = 0.f, s1b = 0.f, s2b = 0.f;
#pragma unroll
    for (int f = 0; f < 16; f++) {
        int c = (f >> 1) * 16 + (f & 1) * 8 + 2 * (lane & 3);
        float b0 = bias_s[c], b1 = bias_s[c + 1];
        float x;
        x = (fmaxf(acc[f][0] + b0, 0.f) + 1e-6f) * ids; x *= x; acc[f][0] = x; s1a += x; s2a += x * x;
        x = (fmaxf(acc[f][1] + b1, 0.f) + 1e-6f) * ids; x *= x; acc[f][1] = x; s1a += x; s2a += x * x;
        x = (fmaxf(acc[f][2] + b0, 0.f) + 1e-6f) * ids; x *= x; acc[f][2] = x; s1b += x; s2b += x * x;
        x = (fmaxf(acc[f][3] + b1, 0.f) + 1e-6f) * ids; x *= x; acc[f][3] = x; s1b += x; s2b += x * x;
    }
    s1a += __shfl_xor_sync(~0u, s1a, 1); s1a += __shfl_xor_sync(~0u, s1a, 2);
    s2a += __shfl_xor_sync(~0u, s2a, 1); s2a += __shfl_xor_sync(~0u, s2a, 2);
    s1b += __shfl_xor_sync(~0u, s1b, 1); s1b += __shfl_xor_sync(~0u, s1b, 2);
    s2b += __shfl_xor_sync(~0u, s2b, 1); s2b += __shfl_xor_sync(~0u, s2b, 2);
    float sa = sqrtf(s1a) / (sqrtf(s2a) + 1e-8f);
    float sb = sqrtf(s1b) / (sqrtf(s2b) + 1e-8f);
#pragma unroll
    for (int f = 0; f < 16; f++) {
        acc[f][0] *= sa; acc[f][1] *= sa; acc[f][2] *= sb; acc[f][3] *= sb;
    }
}

__device__ __forceinline__ void storeT(__nv_bfloat16* hi, __nv_bfloat16* lo,
                                       int col, int row, float x) {
    __nv_bfloat16 hx = __float2bfloat16(x);
    hi[col * KP + row] = hx;
    lo[col * KP + row] = __float2bfloat16(x - __bfloat162float(hx));
}

// ---------------- K1: phi_q ----------------
__global__ void __launch_bounds__(256, 1)
k1_qphi(const float* __restrict__ q, const float* __restrict__ Wq,
        const float* __restrict__ Wqb, const float* __restrict__ ns) {
    extern __shared__ char smraw[];
    __nv_bfloat16* Ahi = (__nv_bfloat16*)smraw;
    __nv_bfloat16* Alo = Ahi + PLANE;
    __nv_bfloat16* Bhi = Alo + PLANE;
    __nv_bfloat16* Blo = Bhi + PLANE;
    float* sBias = (float*)(Blo + PLANE);
    int t = blockIdx.x, h = blockIdx.y, n0 = t * 128;
    int tid = threadIdx.x, w = tid >> 5, lane = tid & 31;

    if (tid < 128) sBias[tid] = Wqb[h * C + tid];
    load_split_tile(q + (size_t)n0 * C, C, Ahi, Alo);
    load_split_tile(Wq + (size_t)h * C * C, C, Bhi, Blo);
    __syncthreads();

    float acc[16][4];
    ZERO16x4(acc);
    wgemm(acc, Ahi, Alo, Bhi, Blo, w * 16);
    float ids = 1.f / (fabsf(ns[0]) + 1e-6f);
    phi_regs(acc, sBias, ids);

    int rA = n0 + w * 16 + (lane >> 2), rB = rA + 8;
#pragma unroll
    for (int f = 0; f < 16; f++) {
        int c = (f >> 1) * 16 + (f & 1) * 8 + 2 * (lane & 3);
        uint2 p0 = make_uint2(packf(acc[f][0]), packf(acc[f][1]));
        *(uint2*)(g_phiq + ((size_t)rA * H + h) * C + c) = p0;
        uint2 p1 = make_uint2(packf(acc[f][2]), packf(acc[f][3]));
        *(uint2*)(g_phiq + ((size_t)rB * H + h) * C + c) = p1;
    }
}

// ---------------- K2: phi_k, v -> KtV + kss partials ----------------
__global__ void __launch_bounds__(256, 1)
k2_kv(const float* __restrict__ src,
      const float* __restrict__ Wk, const float* __restrict__ Wkb,
      const float* __restrict__ Wv, const float* __restrict__ Wvb,
      const float* __restrict__ ns) {
    extern __shared__ char smraw[];
    __nv_bfloat16* Ahi = (__nv_bfloat16*)smraw;
    __nv_bfloat16* Alo = Ahi + PLANE;
    __nv_bfloat16* Bhi = Alo + PLANE;
    __nv_bfloat16* Blo = Bhi + PLANE;
    __nv_bfloat16* Phi = Blo + PLANE;   // phi_k^T hi  [m][r]
    __nv_bfloat16* Plo = Phi + PLANE;   // phi_k^T lo
    float* sBk = (float*)(Plo + PLANE);
    float* sBv = sBk + 128;
    int cblk = blockIdx.x, h = blockIdx.y;
    int tid = threadIdx.x, w = tid >> 5, lane = tid & 31;
    float ids = 1.f / (fabsf(ns[0]) + 1e-6f);

    if (tid < 128) {
        sBk[tid] = Wkb[h * C + tid];
        sBv[tid] = Wvb[h * C + tid];
    }
    float acc2[16][4];
    ZERO16x4(acc2);
    float kss_loc = 0.f;
    int rA = w * 16 + (lane >> 2), rB = rA + 8;

    for (int s = 0; s < SUBT; s++) {
        int n0 = (cblk * SUBT + s) * 128;
        __syncthreads();  // prior ktv mma done reading Phi/B
        load_split_tile(src + (size_t)n0 * C, C, Ahi, Alo);
        load_split_tile(Wk + (size_t)h * C * C, C, Bhi, Blo);
        __syncthreads();

        float acc[16][4];
        ZERO16x4(acc);
        wgemm(acc, Ahi, Alo, Bhi, Blo, w * 16);
        phi_regs(acc, sBk, ids);
        __syncthreads();  // all warps done reading B (Wk) before overwrite

        // write phi_k^T and load Wv
#pragma unroll
        for (int f = 0; f < 16; f++) {
            int c = (f >> 1) * 16 + (f & 1) * 8 + 2 * (lane & 3);
            storeT(Phi, Plo, c, rA, acc[f][0]);
            storeT(Phi, Plo, c + 1, rA, acc[f][1]);
            storeT(Phi, Plo, c, rB, acc[f][2]);
            storeT(Phi, Plo, c + 1, rB, acc[f][3]);
        }
        load_split_tile(Wv + (size_t)h * C * C, C, Bhi, Blo);
        __syncthreads();

        // kss: per-feature row sums of phi_k^T (hi+lo)
        if (tid < 128) {
            float s0 = 0.f;
#pragma unroll 8
            for (int r = 0; r < 128; r++)
                s0 += __bfloat162float(Phi[tid * KP + r]) + __bfloat162float(Plo[tid * KP + r]);
            kss_loc += s0;
        }

        // v GEMM
        ZERO16x4(acc);
        wgemm(acc, Ahi, Alo, Bhi, Blo, w * 16);
#pragma unroll
        for (int f = 0; f < 16; f++) {
            int c = (f >> 1) * 16 + (f & 1) * 8 + 2 * (lane & 3);
            acc[f][0] += sBv[c]; acc[f][1] += sBv[c + 1];
            acc[f][2] += sBv[c]; acc[f][3] += sBv[c + 1];
        }
        __syncthreads();  // all warps done reading B (Wv)
        // write v^T into B planes
#pragma unroll
        for (int f = 0; f < 16; f++) {
            int c = (f >> 1) * 16 + (f & 1) * 8 + 2 * (lane & 3);
            storeT(Bhi, Blo, c, rA, acc[f][0]);
            storeT(Bhi, Blo, c + 1, rA, acc[f][1]);
            storeT(Bhi, Blo, c, rB, acc[f][2]);
            storeT(Bhi, Blo, c + 1, rB, acc[f][3]);
        }
        __syncthreads();

        // ktv: [m][d] += phi_k^T @ (v^T)^T  (contraction over r)
        wgemm(acc2, Phi, Plo, Bhi, Blo, w * 16);
    }

    size_t base = ((size_t)(cblk * H + h)) * C * C;
#pragma unroll
    for (int f = 0; f < 16; f++) {
        int c = (f >> 1) * 16 + (f & 1) * 8 + 2 * (lane & 3);
        *(float2*)(g_ktv_part + base + (size_t)rA * C + c) = make_float2(acc2[f][0], acc2[f][1]);
        *(float2*)(g_ktv_part + base + (size_t)rB * C + c) = make_float2(acc2[f][2], acc2[f][3]);
    }
    if (tid < 128)
        g_kss_part[(size_t)(cblk * H + h) * C + tid] = kss_loc;
}

// ---------------- K2b: reduce + transpose + pack ----------------
__global__ void k2b_reduce() {
    int i = blockIdx.x * blockDim.x + threadIdx.x;  // 0..H*C*C-1
    int h = i >> 14, rem = i & 16383, m = rem >> 7, d = rem & 127;
    float s = 0.f;
#pragma unroll 8
    for (int c = 0; c < NC; c++) s += g_ktv_part[(size_t)c * (H * C * C) + i];
    g_ktvP[(h << 14) + (d << 7) + m] = packf(s);
    if (i < H * C) {
        float s2 = 0.f;
#pragma unroll 8
        for (int c = 0; c < NC; c++) s2 += g_kss_part[(size_t)c * (H * C) + i];
        g_kss[i] = s2;
    }
}

// ---------------- Kw: combined vss weights (packed) ----------------
__global__ void __launch_bounds__(256, 1)
kw_comb(const float* __restrict__ Wv, const float* __restrict__ Wvb,
        const float* __restrict__ vmap, const float* __restrict__ vmapb) {
    extern __shared__ char smraw[];
    float* sWb = (float*)smraw;  // [d][i] pitch PITCHF
    int tid = threadIdx.x;
    int lane = tid & 31, w = tid >> 5;
#pragma unroll
    for (int it = 0; it < 64; it++) {
        int idx = tid + it * 256;
        int d = idx >> 7, i = idx & 127;
        float s = 0.f;
#pragma unroll
        for (int h = 0; h < H; h++) s += Wv[((size_t)h * C + d) * C + i];
        sWb[d * PITCHF + i] = s * 0.125f;
    }
    __syncthreads();

    int o = blockIdx.x * 8 + w;
    float r[4] = {0.f, 0.f, 0.f, 0.f};
    for (int d = 0; d < 128; d++) {
        float vm = vmap[(size_t)o * C + d];
#pragma unroll
        for (int k = 0; k < 4; k++) r[k] += vm * sWb[d * PITCHF + lane + 32 * k];
    }
#pragma unroll
    for (int k = 0; k < 4; k++) g_WcombP[(size_t)o * C + lane + 32 * k] = packf(r[k]);

    if (blockIdx.x == 0 && tid < 128) {
        int oo = tid;
        float s = 0.f;
        for (int d = 0; d < 128; d++) {
            float bv = 0.f;
#pragma unroll
            for (int h = 0; h < H; h++) bv += Wvb[h * C + d];
            s += vmap[(size_t)oo * C + d] * (bv * 0.125f);
        }
        g_bcomb[oo] = s + vmapb[oo];
    }
}

// ---------------- K3: numerator + denom + comb + epilogue ----------------
__global__ void __launch_bounds__(256, 1)
k3_out(const float* __restrict__ src, float* __restrict__ out) {
    extern __shared__ char smraw[];
    __nv_bfloat16* Ahi = (__nv_bfloat16*)smraw;
    __nv_bfloat16* Alo = Ahi + PLANE;
    __nv_bfloat16* Bhi = Alo + PLANE;
    __nv_bfloat16* Blo = Bhi + PLANE;
    float* sKss = (float*)(Blo + PLANE);
    float* sDen = sKss + 128;
    int t = blockIdx.x, n0 = t * 128;
    int tid = threadIdx.x, w = tid >> 5, lane = tid & 31;
    int rA = w * 16 + (lane >> 2), rB = rA + 8;

    float outacc[16][4];
    ZERO16x4(outacc);

    for (int h = 0; h < H; h++) {
        __syncthreads();
        load_packed_tile(g_phiq + ((size_t)n0 * H + h) * C, (size_t)H * C, Ahi, Alo);
        load_packed_tile(g_ktvP + ((size_t)h << 14), C, Bhi, Blo);
        if (tid < 128) sKss[tid] = g_kss[h * C + tid];
        __syncthreads();

        if (tid < 128) {
            float dsum = 0.f;
#pragma unroll 8
            for (int m = 0; m < 128; m++)
                dsum += (__bfloat162float(Ahi[tid * KP + m]) +
                         __bfloat162float(Alo[tid * KP + m])) * sKss[m];
            sDen[tid] = 0.125f / (dsum + 1e-6f);
        }
        __syncthreads();

        float acc[16][4];
        ZERO16x4(acc);
        wgemm(acc, Ahi, Alo, Bhi, Blo, w * 16);
        float da = sDen[rA], db = sDen[rB];
#pragma unroll
        for (int f = 0; f < 16; f++) {
            outacc[f][0] += acc[f][0] * da;
            outacc[f][1] += acc[f][1] * da;
            outacc[f][2] += acc[f][2] * db;
            outacc[f][3] += acc[f][3] * db;
        }
    }

    __syncthreads();
    load_split_tile(src + (size_t)n0 * C, C, Ahi, Alo);
    load_packed_tile(g_WcombP, C, Bhi, Blo);
    if (tid < 128) sKss[tid] = g_bcomb[tid];
    __syncthreads();
    {
        float acc[16][4];
        ZERO16x4(acc);
        wgemm(acc, Ahi, Alo, Bhi, Blo, w * 16);
#pragma unroll
        for (int f = 0; f < 16; f++) {
            int c = (f >> 1) * 16 + (f & 1) * 8 + 2 * (lane & 3);
            outacc[f][0] += acc[f][0] + sKss[c];
            outacc[f][1] += acc[f][1] + sKss[c + 1];
            outacc[f][2] += acc[f][2] + sKss[c];
            outacc[f][3] += acc[f][3] + sKss[c + 1];
        }
    }

    // epilogue: time coord (quad reduction) + store
    float ssa = 0.f, ssb = 0.f;
#pragma unroll
    for (int f = 0; f < 16; f++) {
        ssa += outacc[f][0] * outacc[f][0] + outacc[f][1] * outacc[f][1];
        ssb += outacc[f][2] * outacc[f][2] + outacc[f][3] * outacc[f][3];
    }
    ssa += __shfl_xor_sync(~0u, ssa, 1); ssa += __shfl_xor_sync(~0u, ssa, 2);
    ssb += __shfl_xor_sync(~0u, ssb, 1); ssb += __shfl_xor_sync(~0u, ssb, 2);
    float* rowA = out + (size_t)(n0 + rA) * 129;
    float* rowB = out + (size_t)(n0 + rB) * 129;
    if ((lane & 3) == 0) {
        rowA[0] = sqrtf(ssa + 1.0f);
        rowB[0] = sqrtf(ssb + 1.0f);
    }
#pragma unroll
    for (int f = 0; f < 16; f++) {
        int c = (f >> 1) * 16 + (f & 1) * 8 + 2 * (lane & 3);
        rowA[1 + c] = outacc[f][0];
        rowA[2 + c] = outacc[f][1];
        rowB[1 + c] = outacc[f][2];
        rowB[2 + c] = outacc[f][3];
    }
}

// ---------------- launch ----------------
extern "C" void kernel_launch(void* const* d_in, const int* in_sizes, int n_in,
                              void* d_out, int out_size) {
    const float* q     = (const float*)d_in[0];
    const float* src   = (const float*)d_in[1];
    const float* Wq    = (const float*)d_in[2];
    const float* Wqb   = (const float*)d_in[3];
    const float* Wk    = (const float*)d_in[4];
    const float* Wkb   = (const float*)d_in[5];
    const float* Wv    = (const float*)d_in[6];
    const float* Wvb   = (const float*)d_in[7];
    const float* vmap  = (const float*)d_in[8];
    const float* vmapb = (const float*)d_in[9];
    const float* ns    = (const float*)d_in[10];
    float* out = (float*)d_out;

    size_t sm1 = (size_t)4 * PLANE * 2 + 512;          // 139,776 B
    size_t sm2 = (size_t)6 * PLANE * 2 + 1024;         // 209,920 B
    size_t sm3 = (size_t)4 * PLANE * 2 + 1024;         // 140,288 B
    size_t smw = (size_t)128 * PITCHF * 4;             // 67,584 B
    cudaFuncSetAttribute(k1_qphi, cudaFuncAttributeMaxDynamicSharedMemorySize, (int)sm1);
    cudaFuncSetAttribute(k2_kv,   cudaFuncAttributeMaxDynamicSharedMemorySize, (int)sm2);
    cudaFuncSetAttribute(k3_out,  cudaFuncAttributeMaxDynamicSharedMemorySize, (int)sm3);
    cudaFuncSetAttribute(kw_comb, cudaFuncAttributeMaxDynamicSharedMemorySize, (int)smw);

    kw_comb<<<16, 256, smw>>>(Wv, Wvb, vmap, vmapb);
    k1_qphi<<<dim3(NROWS / 128, H), 256, sm1>>>(q, Wq, Wqb, ns);
    k2_kv<<<dim3(NC, H), 256, sm2>>>(src, Wk, Wkb, Wv, Wvb, ns);
    k2b_reduce<<<(H * C * C) / 256, 256>>>();
    k3_out<<<NROWS / 128, 256, sm3>>>(src, out);
}

// round 3
// speedup vs baseline: 2.7097x; 1.0025x over previous
#include <cuda_runtime.h>
#include <cuda_bf16.h>
#include <math.h>
#include <stdint.h>

#define NROWS 32768
#define C 128
#define H 8
#define KP 136                 // bf16 plane row stride (elements); 272B = 17*16B
#define PLANE (128 * KP)       // elems per 128-row plane (34816 B)
#define NC 64
#define SUBT 4
#define PITCHF 132             // fp32 pitch for kw_comb

// ---------------- scratch ----------------
__device__ uint32_t g_phiq[(size_t)NROWS * H * C];   // packed bf16 hi | lo<<16
__device__ float    g_ktv_part[NC * H * C * C];      // [c][h][m][d]
__device__ float    g_kss_part[NC * H * C];
__device__ uint32_t g_ktvP[H * C * C];               // [h][d][m] packed (B operand)
__device__ float    g_kss[H * C];
__device__ uint32_t g_WcombP[C * C];                 // [o][i] packed
__device__ float    g_bcomb[C];

// ---------------- low-level helpers ----------------
__device__ __forceinline__ uint32_t smem_u32(const void* p) {
    return (uint32_t)__cvta_generic_to_shared(p);
}

__device__ __forceinline__ void ldm4(uint32_t r[4], const __nv_bfloat16* p) {
    uint32_t a = smem_u32(p);
    asm volatile("ldmatrix.sync.aligned.m8n8.x4.shared.b16 {%0,%1,%2,%3}, [%4];"
                 : "=r"(r[0]), "=r"(r[1]), "=r"(r[2]), "=r"(r[3]) : "r"(a));
}

__device__ __forceinline__ void mma_bf16(float d[4], const uint32_t a[4],
                                         uint32_t b0, uint32_t b1) {
    asm volatile(
        "mma.sync.aligned.m16n8k16.row.col.f32.bf16.bf16.f32 "
        "{%0,%1,%2,%3},{%4,%5,%6,%7},{%8,%9},{%0,%1,%2,%3};"
        : "+f"(d[0]), "+f"(d[1]), "+f"(d[2]), "+f"(d[3])
        : "r"(a[0]), "r"(a[1]), "r"(a[2]), "r"(a[3]), "r"(b0), "r"(b1));
}

__device__ __forceinline__ uint32_t packf(float x) {
    __nv_bfloat16 h = __float2bfloat16(x);
    __nv_bfloat16 l = __float2bfloat16(x - __bfloat162float(h));
    return (uint32_t)__bfloat16_as_ushort(h) | ((uint32_t)__bfloat16_as_ushort(l) << 16);
}

__device__ __forceinline__ void split2(__nv_bfloat16* hi, __nv_bfloat16* lo,
                                       int off, float x, float y) {
    __nv_bfloat16 hx = __float2bfloat16(x), hy = __float2bfloat16(y);
    __nv_bfloat16 lx = __float2bfloat16(x - __bfloat162float(hx));
    __nv_bfloat16 ly = __float2bfloat16(y - __bfloat162float(hy));
    *(__nv_bfloat162*)(hi + off) = __halves2bfloat162(hx, hy);
    *(__nv_bfloat162*)(lo + off) = __halves2bfloat162(lx, ly);
}

// fp32 gmem tile [128][ldg] -> two bf16 planes [128][KP]
__device__ __forceinline__ void load_split_tile(const float* __restrict__ g, int ldg,
                                                __nv_bfloat16* hi, __nv_bfloat16* lo) {
    int tid = threadIdx.x;
#pragma unroll
    for (int it = 0; it < 16; it++) {
        int idx = tid + it * 256;
        int r = idx >> 5, c = (idx & 31) << 2;
        float4 v = *(const float4*)(g + (size_t)r * ldg + c);
        int o = r * KP + c;
        split2(hi, lo, o, v.x, v.y);
        split2(hi, lo, o + 2, v.z, v.w);
    }
}

// packed gmem tile [128 rows, stride srow uint32] -> two bf16 planes
__device__ __forceinline__ void load_packed_tile(const uint32_t* __restrict__ g, size_t srow,
                                                 __nv_bfloat16* hi, __nv_bfloat16* lo) {
    int tid = threadIdx.x;
#pragma unroll
    for (int it = 0; it < 16; it++) {
        int idx = tid + it * 256;
        int r = idx >> 5, c = (idx & 31) << 2;
        uint4 v = *(const uint4*)(g + (size_t)r * srow + c);
        int o = r * KP + c;
        hi[o + 0] = __ushort_as_bfloat16((unsigned short)(v.x & 0xffff));
        lo[o + 0] = __ushort_as_bfloat16((unsigned short)(v.x >> 16));
        hi[o + 1] = __ushort_as_bfloat16((unsigned short)(v.y & 0xffff));
        lo[o + 1] = __ushort_as_bfloat16((unsigned short)(v.y >> 16));
        hi[o + 2] = __ushort_as_bfloat16((unsigned short)(v.z & 0xffff));
        lo[o + 2] = __ushort_as_bfloat16((unsigned short)(v.z >> 16));
        hi[o + 3] = __ushort_as_bfloat16((unsigned short)(v.w & 0xffff));
        lo[o + 3] = __ushort_as_bfloat16((unsigned short)(v.w >> 16));
    }
}

// warp GEMM: rows [mrow, mrow+16) x all 128 cols, K=128, split-bf16 (3 mma passes)
// acc[f][j]: frag f covers cols (f>>1)*16 + (f&1)*8 + 2*(lane&3) + {0,1}; rows lane>>2 (+8)
__device__ __forceinline__ void wgemm(float acc[16][4],
                                      const __nv_bfloat16* Ahi, const __nv_bfloat16* Alo,
                                      const __nv_bfloat16* Bhi, const __nv_bfloat16* Blo,
                                      int mrow) {
    int lane = threadIdx.x & 31;
    int lr = lane & 15, lc = lane >> 4;
#pragma unroll
    for (int kt = 0; kt < 8; kt++) {
        int aoff = (mrow + lr) * KP + kt * 16 + lc * 8;
        uint32_t ah[4], al[4];
        ldm4(ah, Ahi + aoff);
        ldm4(al, Alo + aoff);
#pragma unroll
        for (int nt = 0; nt < 8; nt++) {
            int boff = (nt * 16 + lr) * KP + kt * 16 + lc * 8;
            uint32_t bh[4], bl[4];
            ldm4(bh, Bhi + boff);
            ldm4(bl, Blo + boff);
            mma_bf16(acc[nt * 2], ah, bh[0], bh[2]);
            mma_bf16(acc[nt * 2], ah, bl[0], bl[2]);
            mma_bf16(acc[nt * 2], al, bh[0], bh[2]);
            mma_bf16(acc[nt * 2 + 1], ah, bh[1], bh[3]);
            mma_bf16(acc[nt * 2 + 1], ah, bl[1], bl[3]);
            mma_bf16(acc[nt * 2 + 1], al, bh[1], bh[3]);
        }
    }
}

#define ZERO16x4(a)                         \
    _Pragma("unroll") for (int _f = 0; _f < 16; _f++) \
        { a[_f][0] = 0.f; a[_f][1] = 0.f; a[_f][2] = 0.f; a[_f][3] = 0.f; }

// bias + relu + eps + scale + square + row-normalize, entirely in registers
__device__ __forceinline__ void phi_regs(float acc[16][4], const float* bias_s, float ids) {
    int lane = threadIdx.x & 31;
    float s1a = 0.f, s2a = 0.f, s1b = 0.f, s2b = 0.f;
#pragma unroll
    for (int f = 0; f < 16; f++) {
        int c = (f >> 1) * 16 + (f & 1) * 8 + 2 * (lane & 3);
        float b0 = bias_s[c], b1 = bias_s[c + 1];
        float x;
        x = (fmaxf(acc[f][0] + b0, 0.f) + 1e-6f) * ids; x *= x; acc[f][0] = x; s1a += x; s2a += x * x;
        x = (fmaxf(acc[f][1] + b1, 0.f) + 1e-6f) * ids; x *= x; acc[f][1] = x; s1a += x; s2a += x * x;
        x = (fmaxf(acc[f][2] + b0, 0.f) + 1e-6f) * ids; x *= x; acc[f][2] = x; s1b += x; s2b += x * x;
        x = (fmaxf(acc[f][3] + b1, 0.f) + 1e-6f) * ids; x *= x; acc[f][3] = x; s1b += x; s2b += x * x;
    }
    s1a += __shfl_xor_sync(~0u, s1a, 1); s1a += __shfl_xor_sync(~0u, s1a, 2);
    s2a += __shfl_xor_sync(~0u, s2a, 1); s2a += __shfl_xor_sync(~0u, s2a, 2);
    s1b += __shfl_xor_sync(~0u, s1b, 1); s1b += __shfl_xor_sync(~0u, s1b, 2);
    s2b += __shfl_xor_sync(~0u, s2b, 1); s2b += __shfl_xor_sync(~0u, s2b, 2);
    float sa = sqrtf(s1a) / (sqrtf(s2a) + 1e-8f);
    float sb = sqrtf(s1b) / (sqrtf(s2b) + 1e-8f);
#pragma unroll
    for (int f = 0; f < 16; f++) {
        acc[f][0] *= sa; acc[f][1] *= sa; acc[f][2] *= sb; acc[f][3] *= sb;
    }
}

__device__ __forceinline__ void storeT(__nv_bfloat16* hi, __nv_bfloat16* lo,
                                       int col, int row, float x) {
    __nv_bfloat16 hx = __float2bfloat16(x);
    hi[col * KP + row] = hx;
    lo[col * KP + row] = __float2bfloat16(x - __bfloat162float(hx));
}

// ---------------- K1: phi_q ----------------
__global__ void __launch_bounds__(256, 1)
k1_qphi(const float* __restrict__ q, const float* __restrict__ Wq,
        const float* __restrict__ Wqb, const float* __restrict__ ns) {
    extern __shared__ char smraw[];
    __nv_bfloat16* Ahi = (__nv_bfloat16*)smraw;
    __nv_bfloat16* Alo = Ahi + PLANE;
    __nv_bfloat16* Bhi = Alo + PLANE;
    __nv_bfloat16* Blo = Bhi + PLANE;
    float* sBias = (float*)(Blo + PLANE);
    int t = blockIdx.x, h = blockIdx.y, n0 = t * 128;
    int tid = threadIdx.x, w = tid >> 5, lane = tid & 31;

    if (tid < 128) sBias[tid] = Wqb[h * C + tid];
    load_split_tile(q + (size_t)n0 * C, C, Ahi, Alo);
    load_split_tile(Wq + (size_t)h * C * C, C, Bhi, Blo);
    __syncthreads();

    float acc[16][4];
    ZERO16x4(acc);
    wgemm(acc, Ahi, Alo, Bhi, Blo, w * 16);
    float ids = 1.f / (fabsf(ns[0]) + 1e-6f);
    phi_regs(acc, sBias, ids);

    int rA = n0 + w * 16 + (lane >> 2), rB = rA + 8;
#pragma unroll
    for (int f = 0; f < 16; f++) {
        int c = (f >> 1) * 16 + (f & 1) * 8 + 2 * (lane & 3);
        uint2 p0 = make_uint2(packf(acc[f][0]), packf(acc[f][1]));
        *(uint2*)(g_phiq + ((size_t)rA * H + h) * C + c) = p0;
        uint2 p1 = make_uint2(packf(acc[f][2]), packf(acc[f][3]));
        *(uint2*)(g_phiq + ((size_t)rB * H + h) * C + c) = p1;
    }
}

// ---------------- K2: phi_k, v -> KtV + kss partials ----------------
__global__ void __launch_bounds__(256, 1)
k2_kv(const float* __restrict__ src,
      const float* __restrict__ Wk, const float* __restrict__ Wkb,
      const float* __restrict__ Wv, const float* __restrict__ Wvb,
      const float* __restrict__ ns) {
    extern __shared__ char smraw[];
    __nv_bfloat16* Ahi = (__nv_bfloat16*)smraw;
    __nv_bfloat16* Alo = Ahi + PLANE;
    __nv_bfloat16* Bhi = Alo + PLANE;
    __nv_bfloat16* Blo = Bhi + PLANE;
    __nv_bfloat16* Phi = Blo + PLANE;   // phi_k^T hi  [m][r]
    __nv_bfloat16* Plo = Phi + PLANE;   // phi_k^T lo
    float* sBk = (float*)(Plo + PLANE);
    float* sBv = sBk + 128;
    int cblk = blockIdx.x, h = blockIdx.y;
    int tid = threadIdx.x, w = tid >> 5, lane = tid & 31;
    float ids = 1.f / (fabsf(ns[0]) + 1e-6f);

    if (tid < 128) {
        sBk[tid] = Wkb[h * C + tid];
        sBv[tid] = Wvb[h * C + tid];
    }
    float acc2[16][4];
    ZERO16x4(acc2);
    float kss_loc = 0.f;
    int rA = w * 16 + (lane >> 2), rB = rA + 8;

    for (int s = 0; s < SUBT; s++) {
        int n0 = (cblk * SUBT + s) * 128;
        __syncthreads();  // prior ktv mma done reading Phi/B
        load_split_tile(src + (size_t)n0 * C, C, Ahi, Alo);
        load_split_tile(Wk + (size_t)h * C * C, C, Bhi, Blo);
        __syncthreads();

        float acc[16][4];
        ZERO16x4(acc);
        wgemm(acc, Ahi, Alo, Bhi, Blo, w * 16);
        phi_regs(acc, sBk, ids);
        __syncthreads();  // all warps done reading B (Wk) before overwrite

        // write phi_k^T and load Wv
#pragma unroll
        for (int f = 0; f < 16; f++) {
            int c = (f >> 1) * 16 + (f & 1) * 8 + 2 * (lane & 3);
            storeT(Phi, Plo, c, rA, acc[f][0]);
            storeT(Phi, Plo, c + 1, rA, acc[f][1]);
            storeT(Phi, Plo, c, rB, acc[f][2]);
            storeT(Phi, Plo, c + 1, rB, acc[f][3]);
        }
        load_split_tile(Wv + (size_t)h * C * C, C, Bhi, Blo);
        __syncthreads();

        // kss: per-feature row sums of phi_k^T (hi+lo)
        if (tid < 128) {
            float s0 = 0.f;
#pragma unroll 8
            for (int r = 0; r < 128; r++)
                s0 += __bfloat162float(Phi[tid * KP + r]) + __bfloat162float(Plo[tid * KP + r]);
            kss_loc += s0;
        }

        // v GEMM
        ZERO16x4(acc);
        wgemm(acc, Ahi, Alo, Bhi, Blo, w * 16);
#pragma unroll
        for (int f = 0; f < 16; f++) {
            int c = (f >> 1) * 16 + (f & 1) * 8 + 2 * (lane & 3);
            acc[f][0] += sBv[c]; acc[f][1] += sBv[c + 1];
            acc[f][2] += sBv[c]; acc[f][3] += sBv[c + 1];
        }
        __syncthreads();  // all warps done reading B (Wv)
        // write v^T into B planes
#pragma unroll
        for (int f = 0; f < 16; f++) {
            int c = (f >> 1) * 16 + (f & 1) * 8 + 2 * (lane & 3);
            storeT(Bhi, Blo, c, rA, acc[f][0]);
            storeT(Bhi, Blo, c + 1, rA, acc[f][1]);
            storeT(Bhi, Blo, c, rB, acc[f][2]);
            storeT(Bhi, Blo, c + 1, rB, acc[f][3]);
        }
        __syncthreads();

        // ktv: [m][d] += phi_k^T @ (v^T)^T  (contraction over r)
        wgemm(acc2, Phi, Plo, Bhi, Blo, w * 16);
    }

    size_t base = ((size_t)(cblk * H + h)) * C * C;
#pragma unroll
    for (int f = 0; f < 16; f++) {
        int c = (f >> 1) * 16 + (f & 1) * 8 + 2 * (lane & 3);
        *(float2*)(g_ktv_part + base + (size_t)rA * C + c) = make_float2(acc2[f][0], acc2[f][1]);
        *(float2*)(g_ktv_part + base + (size_t)rB * C + c) = make_float2(acc2[f][2], acc2[f][3]);
    }
    if (tid < 128)
        g_kss_part[(size_t)(cblk * H + h) * C + tid] = kss_loc;
}

// ---------------- K2b: reduce + transpose + pack ----------------
__global__ void k2b_reduce() {
    int i = blockIdx.x * blockDim.x + threadIdx.x;  // 0..H*C*C-1
    int h = i >> 14, rem = i & 16383, m = rem >> 7, d = rem & 127;
    float s = 0.f;
#pragma unroll 8
    for (int c = 0; c < NC; c++) s += g_ktv_part[(size_t)c * (H * C * C) + i];
    g_ktvP[(h << 14) + (d << 7) + m] = packf(s);
    if (i < H * C) {
        float s2 = 0.f;
#pragma unroll 8
        for (int c = 0; c < NC; c++) s2 += g_kss_part[(size_t)c * (H * C) + i];
        g_kss[i] = s2;
    }
}

// ---------------- Kw: combined vss weights (packed) ----------------
__global__ void __launch_bounds__(256, 1)
kw_comb(const float* __restrict__ Wv, const float* __restrict__ Wvb,
        const float* __restrict__ vmap, const float* __restrict__ vmapb) {
    extern __shared__ char smraw[];
    float* sWb = (float*)smraw;  // [d][i] pitch PITCHF
    int tid = threadIdx.x;
    int lane = tid & 31, w = tid >> 5;
#pragma unroll
    for (int it = 0; it < 64; it++) {
        int idx = tid + it * 256;
        int d = idx >> 7, i = idx & 127;
        float s = 0.f;
#pragma unroll
        for (int h = 0; h < H; h++) s += Wv[((size_t)h * C + d) * C + i];
        sWb[d * PITCHF + i] = s * 0.125f;
    }
    __syncthreads();

    int o = blockIdx.x * 8 + w;
    float r[4] = {0.f, 0.f, 0.f, 0.f};
    for (int d = 0; d < 128; d++) {
        float vm = vmap[(size_t)o * C + d];
#pragma unroll
        for (int k = 0; k < 4; k++) r[k] += vm * sWb[d * PITCHF + lane + 32 * k];
    }
#pragma unroll
    for (int k = 0; k < 4; k++) g_WcombP[(size_t)o * C + lane + 32 * k] = packf(r[k]);

    if (blockIdx.x == 0 && tid < 128) {
        int oo = tid;
        float s = 0.f;
        for (int d = 0; d < 128; d++) {
            float bv = 0.f;
#pragma unroll
            for (int h = 0; h < H; h++) bv += Wvb[h * C + d];
            s += vmap[(size_t)oo * C + d] * (bv * 0.125f);
        }
        g_bcomb[oo] = s + vmapb[oo];
    }
}

// ---------------- K3: numerator + denom + comb + epilogue ----------------
__global__ void __launch_bounds__(256, 1)
k3_out(const float* __restrict__ src, float* __restrict__ out) {
    extern __shared__ char smraw[];
    __nv_bfloat16* Ahi = (__nv_bfloat16*)smraw;
    __nv_bfloat16* Alo = Ahi + PLANE;
    __nv_bfloat16* Bhi = Alo + PLANE;
    __nv_bfloat16* Blo = Bhi + PLANE;
    float* sKss = (float*)(Blo + PLANE);
    float* sDen = sKss + 128;
    int t = blockIdx.x, n0 = t * 128;
    int tid = threadIdx.x, w = tid >> 5, lane = tid & 31;
    int rA = w * 16 + (lane >> 2), rB = rA + 8;

    float outacc[16][4];
    ZERO16x4(outacc);

    for (int h = 0; h < H; h++) {
        __syncthreads();
        load_packed_tile(g_phiq + ((size_t)n0 * H + h) * C, (size_t)H * C, Ahi, Alo);
        load_packed_tile(g_ktvP + ((size_t)h << 14), C, Bhi, Blo);
        if (tid < 128) sKss[tid] = g_kss[h * C + tid];
        __syncthreads();

        if (tid < 128) {
            float dsum = 0.f;
#pragma unroll 8
            for (int m = 0; m < 128; m++)
                dsum += (__bfloat162float(Ahi[tid * KP + m]) +
                         __bfloat162float(Alo[tid * KP + m])) * sKss[m];
            sDen[tid] = 0.125f / (dsum + 1e-6f);
        }
        __syncthreads();

        float acc[16][4];
        ZERO16x4(acc);
        wgemm(acc, Ahi, Alo, Bhi, Blo, w * 16);
        float da = sDen[rA], db = sDen[rB];
#pragma unroll
        for (int f = 0; f < 16; f++) {
            outacc[f][0] += acc[f][0] * da;
            outacc[f][1] += acc[f][1] * da;
            outacc[f][2] += acc[f][2] * db;
            outacc[f][3] += acc[f][3] * db;
        }
    }

    __syncthreads();
    load_split_tile(src + (size_t)n0 * C, C, Ahi, Alo);
    load_packed_tile(g_WcombP, C, Bhi, Blo);
    if (tid < 128) sKss[tid] = g_bcomb[tid];
    __syncthreads();
    {
        float acc[16][4];
        ZERO16x4(acc);
        wgemm(acc, Ahi, Alo, Bhi, Blo, w * 16);
#pragma unroll
        for (int f = 0; f < 16; f++) {
            int c = (f >> 1) * 16 + (f & 1) * 8 + 2 * (lane & 3);
            outacc[f][0] += acc[f][0] + sKss[c];
            outacc[f][1] += acc[f][1] + sKss[c + 1];
            outacc[f][2] += acc[f][2] + sKss[c];
            outacc[f][3] += acc[f][3] + sKss[c + 1];
        }
    }

    // epilogue: time coord (quad reduction) + store
    float ssa = 0.f, ssb = 0.f;
#pragma unroll
    for (int f = 0; f < 16; f++) {
        ssa += outacc[f][0] * outacc[f][0] + outacc[f][1] * outacc[f][1];
        ssb += outacc[f][2] * outacc[f][2] + outacc[f][3] * outacc[f][3];
    }
    ssa += __shfl_xor_sync(~0u, ssa, 1); ssa += __shfl_xor_sync(~0u, ssa, 2);
    ssb += __shfl_xor_sync(~0u, ssb, 1); ssb += __shfl_xor_sync(~0u, ssb, 2);
    float* rowA = out + (size_t)(n0 + rA) * 129;
    float* rowB = out + (size_t)(n0 + rB) * 129;
    if ((lane & 3) == 0) {
        rowA[0] = sqrtf(ssa + 1.0f);
        rowB[0] = sqrtf(ssb + 1.0f);
    }
#pragma unroll
    for (int f = 0; f < 16; f++) {
        int c = (f >> 1) * 16 + (f & 1) * 8 + 2 * (lane & 3);
        rowA[1 + c] = outacc[f][0];
        rowA[2 + c] = outacc[f][1];
        rowB[1 + c] = outacc[f][2];
        rowB[2 + c] = outacc[f][3];
    }
}

// ---------------- launch ----------------
extern "C" void kernel_launch(void* const* d_in, const int* in_sizes, int n_in,
                              void* d_out, int out_size) {
    const float* q     = (const float*)d_in[0];
    const float* src   = (const float*)d_in[1];
    const float* Wq    = (const float*)d_in[2];
    const float* Wqb   = (const float*)d_in[3];
    const float* Wk    = (const float*)d_in[4];
    const float* Wkb   = (const float*)d_in[5];
    const float* Wv    = (const float*)d_in[6];
    const float* Wvb   = (const float*)d_in[7];
    const float* vmap  = (const float*)d_in[8];
    const float* vmapb = (const float*)d_in[9];
    const float* ns    = (const float*)d_in[10];
    float* out = (float*)d_out;

    size_t sm1 = (size_t)4 * PLANE * 2 + 512;          // 139,776 B
    size_t sm2 = (size_t)6 * PLANE * 2 + 1024;         // 209,920 B
    size_t sm3 = (size_t)4 * PLANE * 2 + 1024;         // 140,288 B
    size_t smw = (size_t)128 * PITCHF * 4;             // 67,584 B
    cudaFuncSetAttribute(k1_qphi, cudaFuncAttributeMaxDynamicSharedMemorySize, (int)sm1);
    cudaFuncSetAttribute(k2_kv,   cudaFuncAttributeMaxDynamicSharedMemorySize, (int)sm2);
    cudaFuncSetAttribute(k3_out,  cudaFuncAttributeMaxDynamicSharedMemorySize, (int)sm3);
    cudaFuncSetAttribute(kw_comb, cudaFuncAttributeMaxDynamicSharedMemorySize, (int)smw);

    kw_comb<<<16, 256, smw>>>(Wv, Wvb, vmap, vmapb);
    k1_qphi<<<dim3(NROWS / 128, H), 256, sm1>>>(q, Wq, Wqb, ns);
    k2_kv<<<dim3(NC, H), 256, sm2>>>(src, Wk, Wkb, Wv, Wvb, ns);
    k2b_reduce<<<(H * C * C) / 256, 256>>>();
    k3_out<<<NROWS / 128, 256, sm3>>>(src, out);
}